// round 15
// baseline (speedup 1.0000x reference)
#include <cuda_runtime.h>
#include <cuda_bf16.h>
#include <math.h>

// Problem constants
#define B_ 2
#define L_ 1024
#define H_ 256
#define NH_ 8
#define DH_ 32
#define FF_ 1024
#define NL_ 2
#define REL_ 100
#define M_ (B_ * L_)            // 2048 rows
#define INV_SCALE 0.17677669529663687f   // 1/sqrt(32)
#define EPS_ 1e-5f

// ---------------- scratch (device globals; no runtime alloc) ----------------
__device__ float g_x[M_ * H_];
__device__ float g_q[M_ * H_];
__device__ float g_k[M_ * H_];
__device__ float g_v[M_ * H_];
__device__ float g_ao[M_ * H_];
__device__ float g_tmp[4 * M_ * H_];          // up to 4 split-K partial buffers
__device__ float g_ffh[M_ * FF_];
__device__ int   g_mask_mode;                 // 0=int32, 1=uint8, 2=float32

// ---------------- mask dtype detection (deterministic) ----------------
__global__ void detect_mask_kernel(const unsigned char* __restrict__ m) {
    if (threadIdx.x == 0 && blockIdx.x == 0) {
        bool nz12 = false, nz3 = false;
        for (int i = 0; i < 16384; i++) {
            unsigned char v = m[i];
            if (v) {
                int o = i & 3;
                if (o == 1 || o == 2) nz12 = true;
                else if (o == 3) nz3 = true;
            }
        }
        g_mask_mode = nz12 ? 1 : (nz3 ? 2 : 0);
    }
}

__device__ __forceinline__ float mask_neg(const void* maskp, int mm, int idx) {
    if (mm == 0) return ((const int*)maskp)[idx] ? -1e20f : 0.0f;
    if (mm == 1) return ((const unsigned char*)maskp)[idx] ? -1e20f : 0.0f;
    return (((const float*)maskp)[idx] != 0.0f) ? -1e20f : 0.0f;
}

// ---------------- simple copy ----------------
__global__ void copy_kernel(const float* __restrict__ src, float* __restrict__ dst, int n) {
    int i = blockIdx.x * blockDim.x + threadIdx.x;
    if (i < n) dst[i] = src[i];
}

// ---------------- SGEMM: 64x64 tile, BK=16, double-buffered ----------------
// mode 0: single GEMM. mode 1: QKV (z selects B/C of 3).
// mode 2: split-K, z writes its partial to C + z*M*N (no atomics).
__global__ __launch_bounds__(256) void sgemm2(
    const float* __restrict__ A,
    const float* __restrict__ B0, const float* __restrict__ B1, const float* __restrict__ B2,
    float* __restrict__ C0, float* __restrict__ C1, float* __restrict__ C2,
    int M, int N, int K,
    const float* __restrict__ bias, int dorelu, int mode, int nsplit)
{
    __shared__ float As[2][64][17];
    __shared__ float Bs[2][16][64];
    int t = threadIdx.x;
    int tx = t & 15, ty = t >> 4;
    int m0 = blockIdx.y * 64, n0 = blockIdx.x * 64;
    int z = blockIdx.z;

    const float* Bm = B0;
    float* C = C0;
    int Kc = K, k0 = 0;
    if (mode == 1) {
        Bm = (z == 0) ? B0 : (z == 1) ? B1 : B2;
        C  = (z == 0) ? C0 : (z == 1) ? C1 : C2;
    } else if (mode == 2) {
        Kc = K / nsplit;
        k0 = z * Kc;
        C = C0 + (size_t)z * M * N;
    }

    int arow = t >> 2, acol = (t & 3) * 4;
    int brow = t >> 4, bcol = (t & 15) * 4;
    const float* Aptr = A + (m0 + arow) * K + k0 + acol;
    const float* Bptr = Bm + (k0 + brow) * N + n0 + bcol;

    float4 av = *(const float4*)Aptr;
    float4 bv = *(const float4*)Bptr;
    As[0][arow][acol + 0] = av.x; As[0][arow][acol + 1] = av.y;
    As[0][arow][acol + 2] = av.z; As[0][arow][acol + 3] = av.w;
    *(float4*)&Bs[0][brow][bcol] = bv;
    __syncthreads();

    float acc[4][4] = {};
    int nk = Kc / 16;
    int buf = 0;
    for (int kb = 0; kb < nk; kb++) {
        if (kb + 1 < nk) {
            av = *(const float4*)(Aptr + (kb + 1) * 16);
            bv = *(const float4*)(Bptr + (size_t)(kb + 1) * 16 * N);
        }
#pragma unroll
        for (int k2 = 0; k2 < 16; k2++) {
            float a0 = As[buf][ty * 4 + 0][k2];
            float a1 = As[buf][ty * 4 + 1][k2];
            float a2 = As[buf][ty * 4 + 2][k2];
            float a3 = As[buf][ty * 4 + 3][k2];
            float4 b4 = *(float4*)&Bs[buf][k2][tx * 4];
            acc[0][0] += a0 * b4.x; acc[0][1] += a0 * b4.y; acc[0][2] += a0 * b4.z; acc[0][3] += a0 * b4.w;
            acc[1][0] += a1 * b4.x; acc[1][1] += a1 * b4.y; acc[1][2] += a1 * b4.z; acc[1][3] += a1 * b4.w;
            acc[2][0] += a2 * b4.x; acc[2][1] += a2 * b4.y; acc[2][2] += a2 * b4.z; acc[2][3] += a2 * b4.w;
            acc[3][0] += a3 * b4.x; acc[3][1] += a3 * b4.y; acc[3][2] += a3 * b4.z; acc[3][3] += a3 * b4.w;
        }
        if (kb + 1 < nk) {
            int nb = buf ^ 1;
            As[nb][arow][acol + 0] = av.x; As[nb][arow][acol + 1] = av.y;
            As[nb][arow][acol + 2] = av.z; As[nb][arow][acol + 3] = av.w;
            *(float4*)&Bs[nb][brow][bcol] = bv;
            __syncthreads();
            buf = nb;
        }
    }

    int c0 = n0 + tx * 4;
#pragma unroll
    for (int i = 0; i < 4; i++) {
        int r = m0 + ty * 4 + i;
        float4 o;
        o.x = acc[i][0]; o.y = acc[i][1]; o.z = acc[i][2]; o.w = acc[i][3];
        if (dorelu) {
            o.x = fmaxf(o.x + bias[c0 + 0], 0.0f);
            o.y = fmaxf(o.y + bias[c0 + 1], 0.0f);
            o.z = fmaxf(o.z + bias[c0 + 2], 0.0f);
            o.w = fmaxf(o.w + bias[c0 + 3], 0.0f);
        }
        *(float4*)&C[(size_t)r * N + c0] = o;
    }
}

// ---------------- fused flash attention v5: 64-col j tiles, 3 CTAs/SM ----------------
// grid (L/32, NH, B), 256 threads.
// kt/vt XOR swizzle: float4 slot = j*8 + (d4 ^ (j&7)).
// sc rows padded to 68 floats (stride 68 => AV prob loads hit distinct banks).
#define A5_KT   0                           // 2048 (Ek/Ev staging spans kt+vt)
#define A5_VT   2048                        // 2048
#define A5_QS   4096                        // 1024
#define A5_SC   5120                        // 32*68 = 2176 (epilogue oh aliases sc+qr)
#define A5_QR   7296                        // 3200
#define A5_ARL  10496                       // 3200
#define A5_MS   13696                       // 32
#define A5_SS   13728                       // 32
#define A5_FC   13760                       // 32
#define ATTN5_SMEM (13792 * 4)              // 55,168 B -> 3 CTAs/SM

__global__ __launch_bounds__(256, 3) void attn5_kernel(
    const float* __restrict__ q, const float* __restrict__ k,
    const float* __restrict__ v, const float* __restrict__ Ek,
    const int* __restrict__ rel, const void* __restrict__ maskp,
    const float* __restrict__ Ev, float* __restrict__ out)
{
    extern __shared__ float sm[];
    float* kt  = sm + A5_KT;
    float* vt  = sm + A5_VT;
    float* qs  = sm + A5_QS;
    float* sc  = sm + A5_SC;
    float* qr  = sm + A5_QR;
    float* arl = sm + A5_ARL;
    float* m_s = sm + A5_MS;
    float* s_s = sm + A5_SS;
    float* fac = sm + A5_FC;
    float4* kt4 = (float4*)kt;
    float4* vt4 = (float4*)vt;

    int t = threadIdx.x;
    int w = t >> 5, l = t & 31;
    int i0 = blockIdx.x * 32, h = blockIdx.y, b = blockIdx.z;
    int mm = g_mask_mode;

    // ---- prolog: q rows, Ek->kt/vt staging, qrel compute, init ----
    for (int idx = t; idx < 32 * 32; idx += 256) {
        int i = idx >> 5, d = idx & 31;
        qs[i * 32 + d] = q[(b * L_ + i0 + i) * H_ + h * 32 + d];
    }
    for (int idx = t; idx < REL_ * 32; idx += 256) kt[idx] = Ek[idx];  // spans kt+vt
    for (int idx = t; idx < 32 * REL_; idx += 256) arl[idx] = 0.0f;
    if (t < 32) { m_s[t] = -3.4e38f; s_s[t] = 0.0f; }
    __syncthreads();

    {   // qr[i][r] = sum_d qs[i][d] * Ek[r][d]
        int i = t >> 3, l8 = t & 7;
        for (int quad = l8; quad < 25; quad += 8) {
            float a0 = 0.f, a1 = 0.f, a2 = 0.f, a3 = 0.f;
#pragma unroll
            for (int d4 = 0; d4 < 8; d4++) {
                float4 qv = *(float4*)&qs[i * 32 + d4 * 4];
                float4 e0 = *(float4*)&kt[(quad * 4 + 0) * 32 + d4 * 4];
                float4 e1 = *(float4*)&kt[(quad * 4 + 1) * 32 + d4 * 4];
                float4 e2 = *(float4*)&kt[(quad * 4 + 2) * 32 + d4 * 4];
                float4 e3 = *(float4*)&kt[(quad * 4 + 3) * 32 + d4 * 4];
                a0 += qv.x * e0.x + qv.y * e0.y + qv.z * e0.z + qv.w * e0.w;
                a1 += qv.x * e1.x + qv.y * e1.y + qv.z * e1.z + qv.w * e1.w;
                a2 += qv.x * e2.x + qv.y * e2.y + qv.z * e2.z + qv.w * e2.w;
                a3 += qv.x * e3.x + qv.y * e3.y + qv.z * e3.z + qv.w * e3.w;
            }
            qr[i * REL_ + quad * 4 + 0] = a0;
            qr[i * REL_ + quad * 4 + 1] = a1;
            qr[i * REL_ + quad * 4 + 2] = a2;
            qr[i * REL_ + quad * 4 + 3] = a3;
        }
    }

    // AV-thread decomposition: t = jq*64 + rp8*8 + d4i
    int jq  = t >> 6;          // j-quarter 0..3 (16 cols each)
    int rp8 = (t >> 3) & 7;    // row group: rows rp8 + 8k
    int d4i = t & 7;           // dim quad
    float4 o[4];
#pragma unroll
    for (int k4 = 0; k4 < 4; k4++) { o[k4].x = 0.f; o[k4].y = 0.f; o[k4].z = 0.f; o[k4].w = 0.f; }

    int r0 = w * 4;            // scores: warp w owns rows r0..r0+3

    const float4* kg = (const float4*)(k + (size_t)(b * L_) * H_ + h * 32);
    const float4* vg = (const float4*)(v + (size_t)(b * L_) * H_ + h * 32);

    // register prefetch of tile 0 (64 rows => 512 f4 per tensor, 2 per thread)
    float4 pk[2], pv[2];
#pragma unroll
    for (int it = 0; it < 2; it++) {
        int idx = t + it * 256;
        int j = idx >> 3, d4 = idx & 7;
        pk[it] = kg[(size_t)j * 64 + d4];
        pv[it] = vg[(size_t)j * 64 + d4];
    }

    for (int jt = 0; jt < 16; jt++) {
        int j0 = jt * 64;
        __syncthreads();   // previous tile's consumers done with kt/vt/sc (and prolog Ek at jt==0)
        // ---- store prefetched tile to smem (swizzled) ----
#pragma unroll
        for (int it = 0; it < 2; it++) {
            int idx = t + it * 256;
            int j = idx >> 3, d4 = idx & 7;
            int slot = j * 8 + (d4 ^ (j & 7));
            kt4[slot] = pk[it];
            vt4[slot] = pv[it];
        }
        __syncthreads();
        // ---- prefetch next tile ----
        if (jt < 15) {
            int j0n = j0 + 64;
#pragma unroll
            for (int it = 0; it < 2; it++) {
                int idx = t + it * 256;
                int j = idx >> 3, d4 = idx & 7;
                pk[it] = kg[(size_t)(j0n + j) * 64 + d4];
                pv[it] = vg[(size_t)(j0n + j) * 64 + d4];
            }
        }

        // ---- hoisted rel/mask loads (overlap QK compute) ----
        unsigned rid_p[4];
        unsigned mbits = 0;
#pragma unroll
        for (int rr = 0; rr < 4; rr++) {
            int base = (b * L_ + i0 + r0 + rr) * L_ + j0 + l;
            unsigned pkk = (unsigned)rel[base] | ((unsigned)rel[base + 32] << 8);
            if (mask_neg(maskp, mm, base) != 0.0f)      mbits |= 1u << (rr * 2 + 0);
            if (mask_neg(maskp, mm, base + 32) != 0.0f) mbits |= 1u << (rr * 2 + 1);
            rid_p[rr] = pkk;
        }

        // ---- scores: 4 rows x 2 cols per thread ----
        float acc[4][2] = {};
#pragma unroll
        for (int d4 = 0; d4 < 8; d4++) {
            float4 qv0 = *(float4*)&qs[(r0 + 0) * 32 + d4 * 4];
            float4 qv1 = *(float4*)&qs[(r0 + 1) * 32 + d4 * 4];
            float4 qv2 = *(float4*)&qs[(r0 + 2) * 32 + d4 * 4];
            float4 qv3 = *(float4*)&qs[(r0 + 3) * 32 + d4 * 4];
#pragma unroll
            for (int c = 0; c < 2; c++) {
                int j = l + 32 * c;
                float4 kv = kt4[j * 8 + (d4 ^ (j & 7))];
                acc[0][c] += qv0.x * kv.x + qv0.y * kv.y + qv0.z * kv.z + qv0.w * kv.w;
                acc[1][c] += qv1.x * kv.x + qv1.y * kv.y + qv1.z * kv.z + qv1.w * kv.w;
                acc[2][c] += qv2.x * kv.x + qv2.y * kv.y + qv2.z * kv.z + qv2.w * kv.w;
                acc[3][c] += qv3.x * kv.x + qv3.y * kv.y + qv3.z * kv.z + qv3.w * kv.w;
            }
        }

        // ---- per-row: finish scores, online softmax, bin ----
#pragma unroll
        for (int rr = 0; rr < 4; rr++) {
            int i = r0 + rr;
            int rid0 = rid_p[rr] & 0xFF;
            int rid1 = (rid_p[rr] >> 8) & 0xFF;
            float s0 = (acc[rr][0] + qr[i * REL_ + rid0]) * INV_SCALE
                       + (((mbits >> (rr * 2 + 0)) & 1u) ? -1e20f : 0.0f);
            float s1 = (acc[rr][1] + qr[i * REL_ + rid1]) * INV_SCALE
                       + (((mbits >> (rr * 2 + 1)) & 1u) ? -1e20f : 0.0f);
            float mx = fmaxf(s0, s1);
#pragma unroll
            for (int off = 16; off; off >>= 1) mx = fmaxf(mx, __shfl_xor_sync(0xffffffffu, mx, off));
            float m_old = m_s[i];
            float m_new = fmaxf(m_old, mx);
            float f = __expf(m_old - m_new);
            if (f != 1.0f) {   // rescale bins only when the max moved (warp-uniform)
                for (int r = l; r < REL_; r += 32) arl[i * REL_ + r] *= f;
            }
            float p0 = __expf(s0 - m_new);
            float p1 = __expf(s1 - m_new);
            sc[i * 68 + l]      = p0;
            sc[i * 68 + l + 32] = p1;
            if (p0 != 0.0f) atomicAdd(&arl[i * REL_ + rid0], p0);
            if (p1 != 0.0f) atomicAdd(&arl[i * REL_ + rid1], p1);
            float ssum = p0 + p1;
#pragma unroll
            for (int off = 16; off; off >>= 1) ssum += __shfl_xor_sync(0xffffffffu, ssum, off);
            if (l == 0) { m_s[i] = m_new; s_s[i] = s_s[i] * f + ssum; fac[i] = f; }
        }
        __syncthreads();   // fac + all rows' probs visible

        // ---- AV: 4 rows x 4 dims x 16 cols per thread, float4 prob loads ----
        float f0 = fac[rp8 + 0], f1 = fac[rp8 + 8], f2 = fac[rp8 + 16], f3 = fac[rp8 + 24];
        o[0].x *= f0; o[0].y *= f0; o[0].z *= f0; o[0].w *= f0;
        o[1].x *= f1; o[1].y *= f1; o[1].z *= f1; o[1].w *= f1;
        o[2].x *= f2; o[2].y *= f2; o[2].z *= f2; o[2].w *= f2;
        o[3].x *= f3; o[3].y *= f3; o[3].z *= f3; o[3].w *= f3;
        int jlo = jq * 16;
#pragma unroll
        for (int gq = 0; gq < 4; gq++) {
            int j = jlo + gq * 4;
            float4 p0 = *(float4*)&sc[(rp8 + 0) * 68 + j];
            float4 p1 = *(float4*)&sc[(rp8 + 8) * 68 + j];
            float4 p2 = *(float4*)&sc[(rp8 + 16) * 68 + j];
            float4 p3 = *(float4*)&sc[(rp8 + 24) * 68 + j];
            float4 v0 = vt4[(j + 0) * 8 + (d4i ^ ((j + 0) & 7))];
            float4 v1 = vt4[(j + 1) * 8 + (d4i ^ ((j + 1) & 7))];
            float4 v2 = vt4[(j + 2) * 8 + (d4i ^ ((j + 2) & 7))];
            float4 v3 = vt4[(j + 3) * 8 + (d4i ^ ((j + 3) & 7))];
            o[0].x += p0.x * v0.x + p0.y * v1.x + p0.z * v2.x + p0.w * v3.x;
            o[0].y += p0.x * v0.y + p0.y * v1.y + p0.z * v2.y + p0.w * v3.y;
            o[0].z += p0.x * v0.z + p0.y * v1.z + p0.z * v2.z + p0.w * v3.z;
            o[0].w += p0.x * v0.w + p0.y * v1.w + p0.z * v2.w + p0.w * v3.w;
            o[1].x += p1.x * v0.x + p1.y * v1.x + p1.z * v2.x + p1.w * v3.x;
            o[1].y += p1.x * v0.y + p1.y * v1.y + p1.z * v2.y + p1.w * v3.y;
            o[1].z += p1.x * v0.z + p1.y * v1.z + p1.z * v2.z + p1.w * v3.z;
            o[1].w += p1.x * v0.w + p1.y * v1.w + p1.z * v2.w + p1.w * v3.w;
            o[2].x += p2.x * v0.x + p2.y * v1.x + p2.z * v2.x + p2.w * v3.x;
            o[2].y += p2.x * v0.y + p2.y * v1.y + p2.z * v2.y + p2.w * v3.y;
            o[2].z += p2.x * v0.z + p2.y * v1.z + p2.z * v2.z + p2.w * v3.z;
            o[2].w += p2.x * v0.w + p2.y * v1.w + p2.z * v2.w + p2.w * v3.w;
            o[3].x += p3.x * v0.x + p3.y * v1.x + p3.z * v2.x + p3.w * v3.x;
            o[3].y += p3.x * v0.y + p3.y * v1.y + p3.z * v2.y + p3.w * v3.y;
            o[3].z += p3.x * v0.z + p3.y * v1.z + p3.z * v2.z + p3.w * v3.z;
            o[3].w += p3.x * v0.w + p3.y * v1.w + p3.z * v2.w + p3.w * v3.w;
        }
    }

    // ---- epilogue (oh aliases sc+qr; Ev staged in kt+vt) ----
    __syncthreads();
    float* oh = sc;
    for (int idx = t; idx < REL_ * 32; idx += 256) kt[idx] = Ev[idx];
    int slot = rp8 * 8 + d4i;
    if (jq > 0) {
        float4* dst = (float4*)&oh[((jq - 1) * 64 + slot) * 16];
#pragma unroll
        for (int k4 = 0; k4 < 4; k4++) dst[k4] = o[k4];
    }
    __syncthreads();
    if (jq == 0) {
#pragma unroll
        for (int qq = 0; qq < 3; qq++) {
            float4* src = (float4*)&oh[(qq * 64 + slot) * 16];
#pragma unroll
            for (int k4 = 0; k4 < 4; k4++) {
                float4 s4 = src[k4];
                o[k4].x += s4.x; o[k4].y += s4.y; o[k4].z += s4.z; o[k4].w += s4.w;
            }
        }
#pragma unroll 4
        for (int r = 0; r < REL_; r++) {
            float4 e = *(float4*)&kt[r * 32 + d4i * 4];
            float w0 = arl[(rp8 + 0) * REL_ + r];
            float w1 = arl[(rp8 + 8) * REL_ + r];
            float w2 = arl[(rp8 + 16) * REL_ + r];
            float w3 = arl[(rp8 + 24) * REL_ + r];
            o[0].x += w0 * e.x; o[0].y += w0 * e.y; o[0].z += w0 * e.z; o[0].w += w0 * e.w;
            o[1].x += w1 * e.x; o[1].y += w1 * e.y; o[1].z += w1 * e.z; o[1].w += w1 * e.w;
            o[2].x += w2 * e.x; o[2].y += w2 * e.y; o[2].z += w2 * e.z; o[2].w += w2 * e.w;
            o[3].x += w3 * e.x; o[3].y += w3 * e.y; o[3].z += w3 * e.z; o[3].w += w3 * e.w;
        }
#pragma unroll
        for (int k4 = 0; k4 < 4; k4++) {
            int r = rp8 + 8 * k4;
            float inv = 1.0f / s_s[r];
            float4 o4;
            o4.x = o[k4].x * inv; o4.y = o[k4].y * inv; o4.z = o[k4].z * inv; o4.w = o[k4].w * inv;
            *(float4*)&out[(size_t)(b * L_ + i0 + r) * H_ + h * 32 + d4i * 4] = o4;
        }
    }
}

// ---------------- bias + residual + LayerNorm; sums nbuf split-K partials ----------------
__global__ __launch_bounds__(256) void ln_kernel(
    const float* __restrict__ tin, const float* __restrict__ bias,
    const float* __restrict__ resid, const float* __restrict__ gam,
    const float* __restrict__ bet, float* __restrict__ out, int nbuf)
{
    int row = blockIdx.x, c = threadIdx.x;
    float vv = bias[c] + resid[row * H_ + c];
    for (int s = 0; s < nbuf; s++) vv += tin[(size_t)s * M_ * H_ + row * H_ + c];
    __shared__ float red[16];
    float s1 = vv, s2 = vv * vv;
#pragma unroll
    for (int off = 16; off; off >>= 1) {
        s1 += __shfl_xor_sync(0xffffffffu, s1, off);
        s2 += __shfl_xor_sync(0xffffffffu, s2, off);
    }
    int w = c >> 5, l = c & 31;
    if (l == 0) { red[w] = s1; red[8 + w] = s2; }
    __syncthreads();
    float t1 = 0.0f, t2 = 0.0f;
#pragma unroll
    for (int ww = 0; ww < 8; ww++) { t1 += red[ww]; t2 += red[8 + ww]; }
    float mean = t1 * (1.0f / 256.0f);
    float var = t2 * (1.0f / 256.0f) - mean * mean;
    out[row * H_ + c] = (vv - mean) * rsqrtf(var + EPS_) * gam[c] + bet[c];
}

// ---------------- launch ----------------
extern "C" void kernel_launch(void* const* d_in, const int* in_sizes, int n_in,
                              void* d_out, int out_size)
{
    (void)in_sizes; (void)n_in; (void)out_size;
    const float* inputs = (const float*)d_in[0];
    const float* Wq = (const float*)d_in[1];
    const float* Wk = (const float*)d_in[2];
    const float* Wv = (const float*)d_in[3];
    const float* Wo = (const float*)d_in[4];
    const float* bo = (const float*)d_in[5];
    const float* W1 = (const float*)d_in[6];
    const float* b1 = (const float*)d_in[7];
    const float* W2 = (const float*)d_in[8];
    const float* b2 = (const float*)d_in[9];
    const float* ln1g = (const float*)d_in[10];
    const float* ln1b = (const float*)d_in[11];
    const float* ln2g = (const float*)d_in[12];
    const float* ln2b = (const float*)d_in[13];
    const float* Ek = (const float*)d_in[14];
    const float* Ev = (const float*)d_in[15];
    const int*   rel = (const int*)d_in[16];
    const void*  mask = d_in[17];

    float *px, *pq, *pk, *pv, *pao, *ptmp, *pffh;
    cudaGetSymbolAddress((void**)&px,  g_x);
    cudaGetSymbolAddress((void**)&pq,  g_q);
    cudaGetSymbolAddress((void**)&pk,  g_k);
    cudaGetSymbolAddress((void**)&pv,  g_v);
    cudaGetSymbolAddress((void**)&pao, g_ao);
    cudaGetSymbolAddress((void**)&ptmp, g_tmp);
    cudaGetSymbolAddress((void**)&pffh, g_ffh);

    cudaFuncSetAttribute(attn5_kernel, cudaFuncAttributeMaxDynamicSharedMemorySize, ATTN5_SMEM);

    detect_mask_kernel<<<1, 1>>>((const unsigned char*)mask);
    copy_kernel<<<(M_ * H_ + 255) / 256, 256>>>(inputs, px, M_ * H_);

    for (int l = 0; l < NL_; l++) {
        const float* wq = Wq + l * H_ * H_;
        const float* wk = Wk + l * H_ * H_;
        const float* wv = Wv + l * H_ * H_;
        const float* wo = Wo + l * H_ * H_;
        const float* w1 = W1 + l * H_ * FF_;
        const float* w2 = W2 + l * FF_ * H_;

        // fused QKV (one launch, 384 CTAs)
        sgemm2<<<dim3(H_ / 64, M_ / 64, 3), 256>>>(
            px, wq, wk, wv, pq, pk, pv, M_, H_, H_, nullptr, 0, 1, 1);

        attn5_kernel<<<dim3(L_ / 32, NH_, B_), 256, ATTN5_SMEM>>>(
            pq, pk, pv, Ek, rel, mask, Ev, pao);

        // Wo: split-K=2, partials to ptmp[0..1]; ln sums them
        sgemm2<<<dim3(H_ / 64, M_ / 64, 2), 256>>>(
            pao, wo, nullptr, nullptr, ptmp, nullptr, nullptr, M_, H_, H_, nullptr, 0, 2, 2);

        ln_kernel<<<M_, 256>>>(ptmp, bo + l * H_, px, ln1g + l * H_, ln1b + l * H_, px, 2);

        // FF1: bias + relu fused
        sgemm2<<<dim3(FF_ / 64, M_ / 64, 1), 256>>>(
            px, w1, nullptr, nullptr, pffh, nullptr, nullptr, M_, FF_, H_, b1 + l * FF_, 1, 0, 1);

        // FF2: split-K=4, partials to ptmp[0..3]; ln sums them
        sgemm2<<<dim3(H_ / 64, M_ / 64, 4), 256>>>(
            pffh, w2, nullptr, nullptr, ptmp, nullptr, nullptr, M_, H_, FF_, nullptr, 0, 2, 4);

        float* dst = (l == NL_ - 1) ? (float*)d_out : px;
        ln_kernel<<<M_, 256>>>(ptmp, b2 + l * H_, px, ln2g + l * H_, ln2b + l * H_, dst, 4);
    }
}